// round 8
// baseline (speedup 1.0000x reference)
#include <cuda_runtime.h>
#include <cuda_fp16.h>
#include <math.h>

// ---------------------------------------------------------------------------
// Problem constants
// ---------------------------------------------------------------------------
#define N_NODES 50000
#define N_EDGES 800000
#define IN_DIM  128
#define HID     64
#define HEADS   4
#define H1DIM   (HEADS * HID)   // 256
#define OUT_DIM 64
#define NEG_SLOPE 0.2f

// ---------------------------------------------------------------------------
// Device scratch
// ---------------------------------------------------------------------------
__device__ float  g_w1t[IN_DIM * H1DIM];           // tf32-rounded W1
__device__ float  g_w2t[H1DIM * OUT_DIM];          // tf32-rounded W2
__device__ __half g_h1h[(size_t)N_NODES * H1DIM];   // x @ W1 (fp16, for gather)
__device__ float  g_hh [(size_t)N_NODES * H1DIM];   // elu(agg1+b1), tf32-rounded
__device__ __half g_h2h[(size_t)N_NODES * OUT_DIM]; // hh @ W2 (fp16, for gather)
__device__ float g_as1[N_NODES * HEADS];
__device__ float g_ad1[N_NODES * HEADS];
__device__ float g_as2[N_NODES];
__device__ float g_ad2[N_NODES];
__device__ int   g_deg[N_NODES];
__device__ int   g_rowptr[N_NODES + 1];
__device__ int   g_cursor[N_NODES];
__device__ int   g_esrc[N_EDGES];

__device__ __forceinline__ unsigned f2tf32(float f) {
    unsigned r;
    asm("cvt.rna.tf32.f32 %0, %1;" : "=r"(r) : "f"(f));
    return r;
}
__device__ __forceinline__ float tf32r(float f) {
    return __uint_as_float(f2tf32(f));
}

// ---------------------------------------------------------------------------
// One-shot tf32 pre-rounding of the WEIGHTS only (x is converted in-smem
// inside GEMM1). 48K elements, ~1us.
// ---------------------------------------------------------------------------
#define W1Q  ((IN_DIM * H1DIM) / 4)
#define W2Q  ((H1DIM * OUT_DIM) / 4)

__global__ void k_cvt_w(const float* __restrict__ W1,
                        const float* __restrict__ W2) {
    int i = blockIdx.x * blockDim.x + threadIdx.x;
    if (i >= W1Q + W2Q) return;
    const float4* src;
    float4* dst;
    if (i < W1Q) { src = (const float4*)W1 + i;        dst = (float4*)g_w1t + i; }
    else         { src = (const float4*)W2 + (i - W1Q); dst = (float4*)g_w2t + (i - W1Q); }
    float4 v = *src;
    *dst = make_float4(tf32r(v.x), tf32r(v.y), tf32r(v.z), tf32r(v.w));
}

// ---------------------------------------------------------------------------
// CSR build (edge_index arrives as int32; 4 edges/thread for ILP)
// ---------------------------------------------------------------------------
__global__ void k_hist(const int* __restrict__ ei) {
    int base = (blockIdx.x * blockDim.x + threadIdx.x) * 4;
    if (base >= N_EDGES) return;
    int4 d = *(const int4*)(ei + N_EDGES + base);
    atomicAdd(&g_deg[d.x], 1);
    atomicAdd(&g_deg[d.y], 1);
    atomicAdd(&g_deg[d.z], 1);
    atomicAdd(&g_deg[d.w], 1);
}

__global__ void k_scan() {
    __shared__ int sums[1024];
    const int tid = threadIdx.x;
    const int CH = (N_NODES + 1023) / 1024;
    int start = tid * CH;
    int s = 0;
    for (int i = 0; i < CH; i++) {
        int g = start + i;
        if (g < N_NODES) s += g_deg[g];
    }
    sums[tid] = s;
    __syncthreads();
    for (int off = 1; off < 1024; off <<= 1) {
        int v = (tid >= off) ? sums[tid - off] : 0;
        __syncthreads();
        sums[tid] += v;
        __syncthreads();
    }
    int run = (tid == 0) ? 0 : sums[tid - 1];
    for (int i = 0; i < CH; i++) {
        int g = start + i;
        if (g < N_NODES) {
            g_rowptr[g] = run;
            g_cursor[g] = run;
            run += g_deg[g];
        }
    }
    if (tid == 1023) g_rowptr[N_NODES] = run;
}

__global__ void k_fill(const int* __restrict__ ei) {
    int base = (blockIdx.x * blockDim.x + threadIdx.x) * 4;
    if (base >= N_EDGES) return;
    int4 sv = *(const int4*)(ei + base);
    int4 dv = *(const int4*)(ei + N_EDGES + base);
    int p0 = atomicAdd(&g_cursor[dv.x], 1);
    int p1 = atomicAdd(&g_cursor[dv.y], 1);
    int p2 = atomicAdd(&g_cursor[dv.z], 1);
    int p3 = atomicAdd(&g_cursor[dv.w], 1);
    g_esrc[p0] = sv.x;
    g_esrc[p1] = sv.y;
    g_esrc[p2] = sv.z;
    g_esrc[p3] = sv.w;
}

// ---------------------------------------------------------------------------
// TF32 tensor-core GEMM. Block 128x64, 8 warps (4x2), warp tile 32x32,
// mma.sync.m16n8k8, cp.async 2-stage pipeline.
// CVT_A: convert the A tile to tf32 IN SMEM once per tile (each thread
// rounds exactly the 16 floats it cp.async'd) — bit-identical to rounding
// at fragment time, but each element converted once and overlapped with the
// next tile's cp.async issue. B is always pre-rounded.
// Epilogue: fp16 H store + fused attention dots (one head == one col block).
// ---------------------------------------------------------------------------
#define BMg 128
#define BNg 64
#define BKg 32

__device__ __forceinline__ void cp16(unsigned dst, const float* src, bool valid) {
    int sz = valid ? 16 : 0;
    asm volatile("cp.async.cg.shared.global [%0], [%1], 16, %2;\n"
                 :: "r"(dst), "l"(src), "r"(sz));
}
#define CP_COMMIT() asm volatile("cp.async.commit_group;\n" ::: "memory")
#define CP_WAIT0()  asm volatile("cp.async.wait_group 0;\n" ::: "memory")

template <int K, int HEADS_N, bool CVT_A>
__global__ void __launch_bounds__(256) k_gemm_tf32(
    const float* __restrict__ A, const float* __restrict__ B,
    __half* __restrict__ Hout,
    const float* __restrict__ a_src, const float* __restrict__ a_dst,
    float* __restrict__ as_out, float* __restrict__ ad_out)
{
    constexpr int NIT = K / BKg;
    __shared__ __align__(16) float As[2][BMg][BKg + 4];
    __shared__ __align__(16) float Bs[2][BKg][BNg + 8];
    __shared__ float sa[64], sd[64];
    __shared__ float ps_s[2][BMg], pd_s[2][BMg];

    const int tid  = threadIdx.x;
    const int head = blockIdx.x;
    const int row0 = blockIdx.y * BMg;
    const int col0 = head * BNg;
    const int NTOT = HEADS_N * 64;
    const int wid = tid >> 5, lane = tid & 31;
    const int wm = wid & 3, wn = wid >> 2;
    const int g = lane >> 2, t4 = lane & 3;

    if (tid < 64) {
        sa[tid] = a_src[head * 64 + tid];
        sd[tid] = a_dst[head * 64 + tid];
    }

    const int ar = tid >> 3;          // 0..31
    const int ac = (tid & 7) * 4;     // 0..28
    const int br = tid >> 4;          // 0..15
    const int bc = (tid & 15) * 4;    // 0..60

    const unsigned sA = (unsigned)__cvta_generic_to_shared(&As[0][0][0]);
    const unsigned sB = (unsigned)__cvta_generic_to_shared(&Bs[0][0][0]);

    float acc[2][4][4];
#pragma unroll
    for (int i = 0; i < 2; i++)
#pragma unroll
        for (int j = 0; j < 4; j++)
#pragma unroll
            for (int c = 0; c < 4; c++) acc[i][j][c] = 0.f;

    auto issue = [&](int it, int buf) {
        const int kt = it * BKg;
#pragma unroll
        for (int i = 0; i < 4; i++) {
            int r = ar + i * 32;
            int grr = row0 + r;
            bool ok = (grr < N_NODES);
            const float* src = A + (size_t)(ok ? grr : 0) * K + kt + ac;
            cp16(sA + (unsigned)(((buf * BMg + r) * (BKg + 4) + ac) * 4), src, ok);
        }
#pragma unroll
        for (int i = 0; i < 2; i++) {
            int r = br + i * 16;
            const float* src = B + (size_t)(kt + r) * NTOT + col0 + bc;
            cp16(sB + (unsigned)(((buf * BKg + r) * (BNg + 8) + bc) * 4), src, true);
        }
    };

    issue(0, 0);
    CP_COMMIT();

    for (int it = 0; it < NIT; it++) {
        CP_WAIT0();
        __syncthreads();
        const int b = it & 1;
        if (CVT_A) {
            // round own A elements in place (overlaps with next-tile issue)
#pragma unroll
            for (int i = 0; i < 4; i++) {
                float4* pp = (float4*)&As[b][ar + i * 32][ac];
                float4 v = *pp;
                *pp = make_float4(tf32r(v.x), tf32r(v.y), tf32r(v.z), tf32r(v.w));
            }
        }
        if (it + 1 < NIT) {
            issue(it + 1, (it + 1) & 1);
            CP_COMMIT();
        }
        if (CVT_A) __syncthreads();   // conversions visible to all warps
#pragma unroll
        for (int kk = 0; kk < BKg; kk += 8) {
            unsigned af[2][4], bf[4][2];
#pragma unroll
            for (int mf = 0; mf < 2; mf++) {
                int rb = wm * 32 + mf * 16 + g;
                af[mf][0] = __float_as_uint(As[b][rb][kk + t4]);
                af[mf][1] = __float_as_uint(As[b][rb + 8][kk + t4]);
                af[mf][2] = __float_as_uint(As[b][rb][kk + t4 + 4]);
                af[mf][3] = __float_as_uint(As[b][rb + 8][kk + t4 + 4]);
            }
#pragma unroll
            for (int nf = 0; nf < 4; nf++) {
                int n = wn * 32 + nf * 8 + g;
                bf[nf][0] = __float_as_uint(Bs[b][kk + t4][n]);
                bf[nf][1] = __float_as_uint(Bs[b][kk + t4 + 4][n]);
            }
#pragma unroll
            for (int mf = 0; mf < 2; mf++)
#pragma unroll
                for (int nf = 0; nf < 4; nf++) {
                    asm volatile(
                        "mma.sync.aligned.m16n8k8.row.col.f32.tf32.tf32.f32 "
                        "{%0,%1,%2,%3}, {%4,%5,%6,%7}, {%8,%9}, {%0,%1,%2,%3};"
                        : "+f"(acc[mf][nf][0]), "+f"(acc[mf][nf][1]),
                          "+f"(acc[mf][nf][2]), "+f"(acc[mf][nf][3])
                        : "r"(af[mf][0]), "r"(af[mf][1]),
                          "r"(af[mf][2]), "r"(af[mf][3]),
                          "r"(bf[nf][0]), "r"(bf[nf][1]));
                }
        }
    }

    // ---- epilogue: attention dots + fp16 store ----------------------------
    float ps[4] = {0.f, 0.f, 0.f, 0.f}, pd[4] = {0.f, 0.f, 0.f, 0.f};
#pragma unroll
    for (int nf = 0; nf < 4; nf++) {
        int cl = wn * 32 + nf * 8 + 2 * t4;
        float s0 = sa[cl], s1 = sa[cl + 1];
        float d0 = sd[cl], d1 = sd[cl + 1];
#pragma unroll
        for (int mf = 0; mf < 2; mf++) {
            ps[mf * 2 + 0] += acc[mf][nf][0] * s0 + acc[mf][nf][1] * s1;
            ps[mf * 2 + 1] += acc[mf][nf][2] * s0 + acc[mf][nf][3] * s1;
            pd[mf * 2 + 0] += acc[mf][nf][0] * d0 + acc[mf][nf][1] * d1;
            pd[mf * 2 + 1] += acc[mf][nf][2] * d0 + acc[mf][nf][3] * d1;
        }
    }
#pragma unroll
    for (int off = 1; off <= 2; off <<= 1)
#pragma unroll
        for (int i = 0; i < 4; i++) {
            ps[i] += __shfl_xor_sync(~0u, ps[i], off);
            pd[i] += __shfl_xor_sync(~0u, pd[i], off);
        }
    if (t4 == 0) {
        int rb = wm * 32 + g;
        ps_s[wn][rb]      = ps[0]; pd_s[wn][rb]      = pd[0];
        ps_s[wn][rb + 8]  = ps[1]; pd_s[wn][rb + 8]  = pd[1];
        ps_s[wn][rb + 16] = ps[2]; pd_s[wn][rb + 16] = pd[2];
        ps_s[wn][rb + 24] = ps[3]; pd_s[wn][rb + 24] = pd[3];
    }

#pragma unroll
    for (int mf = 0; mf < 2; mf++)
#pragma unroll
        for (int nf = 0; nf < 4; nf++) {
            int r = row0 + wm * 32 + mf * 16 + g;
            int c = col0 + wn * 32 + nf * 8 + 2 * t4;
            if (r < N_NODES)
                *(__half2*)(Hout + (size_t)r * NTOT + c) =
                    __floats2half2_rn(acc[mf][nf][0], acc[mf][nf][1]);
            if (r + 8 < N_NODES)
                *(__half2*)(Hout + (size_t)(r + 8) * NTOT + c) =
                    __floats2half2_rn(acc[mf][nf][2], acc[mf][nf][3]);
        }

    __syncthreads();
    if (tid < BMg) {
        int grr = row0 + tid;
        if (grr < N_NODES) {
            as_out[grr * HEADS_N + head] = ps_s[0][tid] + ps_s[1][tid];
            ad_out[grr * HEADS_N + head] = pd_s[0][tid] + pd_s[1][tid];
        }
    }
}

// ---------------------------------------------------------------------------
// Layer-1 aggregation: warp per destination node, single softmax pass.
// Gathers grouped 4-wide WITH runtime bounds: no dummy traffic (round-6
// lesson) and no deep staging arrays (round-5 lesson); MLP=4.
// ---------------------------------------------------------------------------
__global__ void k_agg1(const float* __restrict__ b1) {
    int d = (blockIdx.x * blockDim.x + threadIdx.x) >> 5;
    if (d >= N_NODES) return;
    int lane = threadIdx.x & 31;
    int row  = g_rowptr[d];
    int tot  = g_rowptr[d + 1] - row + 1;     // +1 self-loop
    const int headA = lane & 3;               // phase head
    const int slotA = lane >> 2;              // phase edge slot (0..7)
    const int headB = lane >> 3;              // dim head

    const float ad_h = g_ad1[d * HEADS + headA];

    float ssum = 0.f;
    float acc[8];
#pragma unroll
    for (int j = 0; j < 8; j++) acc[j] = 0.f;

    auto fma8 = [&](uint4 u, float pe) {
        float2 f0 = __half22float2(*(__half2*)&u.x);
        float2 f1 = __half22float2(*(__half2*)&u.y);
        float2 f2 = __half22float2(*(__half2*)&u.z);
        float2 f3 = __half22float2(*(__half2*)&u.w);
        acc[0] += pe * f0.x; acc[1] += pe * f0.y;
        acc[2] += pe * f1.x; acc[3] += pe * f1.y;
        acc[4] += pe * f2.x; acc[5] += pe * f2.y;
        acc[6] += pe * f3.x; acc[7] += pe * f3.y;
    };

    for (int base = 0; base < tot; base += 8) {
        int idx = base + slotA;
        int s = d;
        float p = 0.f;
        if (idx < tot) {
            if (idx > 0) s = g_esrc[row + idx - 1];
            float v = g_as1[s * HEADS + headA] + ad_h;
            float e = v > 0.f ? v : NEG_SLOPE * v;
            p = __expf(e);
        }
        ssum += p;
        int lim = min(8, tot - base);
        int e2 = 0;
        for (; e2 + 4 <= lim; e2 += 4) {
            float pe0 = __shfl_sync(~0u, p, (e2 + 0) * 4 + headB);
            float pe1 = __shfl_sync(~0u, p, (e2 + 1) * 4 + headB);
            float pe2 = __shfl_sync(~0u, p, (e2 + 2) * 4 + headB);
            float pe3 = __shfl_sync(~0u, p, (e2 + 3) * 4 + headB);
            int sn0 = __shfl_sync(~0u, s, (e2 + 0) * 4);
            int sn1 = __shfl_sync(~0u, s, (e2 + 1) * 4);
            int sn2 = __shfl_sync(~0u, s, (e2 + 2) * 4);
            int sn3 = __shfl_sync(~0u, s, (e2 + 3) * 4);
            uint4 u0 = *((const uint4*)(g_h1h + (size_t)sn0 * H1DIM) + lane);
            uint4 u1 = *((const uint4*)(g_h1h + (size_t)sn1 * H1DIM) + lane);
            uint4 u2 = *((const uint4*)(g_h1h + (size_t)sn2 * H1DIM) + lane);
            uint4 u3 = *((const uint4*)(g_h1h + (size_t)sn3 * H1DIM) + lane);
            fma8(u0, pe0); fma8(u1, pe1); fma8(u2, pe2); fma8(u3, pe3);
        }
        for (; e2 < lim; e2++) {
            float pe = __shfl_sync(~0u, p, e2 * 4 + headB);
            int   sn = __shfl_sync(~0u, s, e2 * 4);
            uint4 u = *((const uint4*)(g_h1h + (size_t)sn * H1DIM) + lane);
            fma8(u, pe);
        }
    }
    ssum += __shfl_xor_sync(~0u, ssum, 4);
    ssum += __shfl_xor_sync(~0u, ssum, 8);
    ssum += __shfl_xor_sync(~0u, ssum, 16);     // total for head (lane&3)
    float den = __shfl_sync(~0u, ssum, headB);  // den for this lane's dim-head
    float inv = 1.f / den;

    float* o = g_hh + (size_t)d * H1DIM + lane * 8;
#pragma unroll
    for (int j = 0; j < 8; j++) {
        float v = acc[j] * inv + b1[lane * 8 + j];
        v = v > 0.f ? v : expm1f(v);             // ELU
        o[j] = tf32r(v);                         // pre-round for gemm2
    }
}

// ---------------------------------------------------------------------------
// Layer-2 aggregation + final fc, 4-wide gather groups with runtime bounds.
// ---------------------------------------------------------------------------
__global__ void k_agg2(const float* __restrict__ b2,
                       const float* __restrict__ fcw,
                       const float* __restrict__ fcb,
                       float* __restrict__ out) {
    int d = (blockIdx.x * blockDim.x + threadIdx.x) >> 5;
    if (d >= N_NODES) return;
    int lane = threadIdx.x & 31;
    int row  = g_rowptr[d];
    int tot  = g_rowptr[d + 1] - row + 1;
    const float ad = g_ad2[d];

    float ssum = 0.f, a0 = 0.f, a1 = 0.f;
    for (int base = 0; base < tot; base += 32) {
        int idx = base + lane;
        int s = d;
        float p = 0.f;
        if (idx < tot) {
            if (idx > 0) s = g_esrc[row + idx - 1];
            float v = g_as2[s] + ad;
            float e = v > 0.f ? v : NEG_SLOPE * v;
            p = __expf(e);
        }
        ssum += p;
        int lim = min(32, tot - base);
        int e2 = 0;
        for (; e2 + 4 <= lim; e2 += 4) {
            float pe0 = __shfl_sync(~0u, p, e2 + 0);
            float pe1 = __shfl_sync(~0u, p, e2 + 1);
            float pe2 = __shfl_sync(~0u, p, e2 + 2);
            float pe3 = __shfl_sync(~0u, p, e2 + 3);
            int sn0 = __shfl_sync(~0u, s, e2 + 0);
            int sn1 = __shfl_sync(~0u, s, e2 + 1);
            int sn2 = __shfl_sync(~0u, s, e2 + 2);
            int sn3 = __shfl_sync(~0u, s, e2 + 3);
            float2 h0 = __half22float2(*((const __half2*)(g_h2h + (size_t)sn0 * OUT_DIM) + lane));
            float2 h1 = __half22float2(*((const __half2*)(g_h2h + (size_t)sn1 * OUT_DIM) + lane));
            float2 h2 = __half22float2(*((const __half2*)(g_h2h + (size_t)sn2 * OUT_DIM) + lane));
            float2 h3 = __half22float2(*((const __half2*)(g_h2h + (size_t)sn3 * OUT_DIM) + lane));
            a0 += pe0 * h0.x + pe1 * h1.x + pe2 * h2.x + pe3 * h3.x;
            a1 += pe0 * h0.y + pe1 * h1.y + pe2 * h2.y + pe3 * h3.y;
        }
        for (; e2 < lim; e2++) {
            float pe = __shfl_sync(~0u, p, e2);
            int   sn = __shfl_sync(~0u, s, e2);
            float2 hv = __half22float2(
                *((const __half2*)(g_h2h + (size_t)sn * OUT_DIM) + lane));
            a0 += pe * hv.x;
            a1 += pe * hv.y;
        }
    }
#pragma unroll
    for (int off = 16; off >= 1; off >>= 1)
        ssum += __shfl_xor_sync(~0u, ssum, off);
    float inv = 1.f / ssum;
    float v0 = a0 * inv + b2[lane * 2];
    float v1 = a1 * inv + b2[lane * 2 + 1];
    float part = v0 * fcw[lane * 2] + v1 * fcw[lane * 2 + 1];
#pragma unroll
    for (int off = 16; off >= 1; off >>= 1)
        part += __shfl_xor_sync(~0u, part, off);
    if (lane == 0) out[d] = part + fcb[0];
}

// ---------------------------------------------------------------------------
// Launch: fork-join — CSR on side stream ∥ (W-cvt + GEMM1) on main stream.
// ---------------------------------------------------------------------------
extern "C" void kernel_launch(void* const* d_in, const int* in_sizes, int n_in,
                              void* d_out, int out_size) {
    const float* x      = (const float*)d_in[0];
    const int*   ei     = (const int*)d_in[1];     // int32 on the wire
    const float* W1     = (const float*)d_in[2];
    const float* a_src1 = (const float*)d_in[3];
    const float* a_dst1 = (const float*)d_in[4];
    const float* b1     = (const float*)d_in[5];
    const float* W2     = (const float*)d_in[6];
    const float* a_src2 = (const float*)d_in[7];
    const float* a_dst2 = (const float*)d_in[8];
    const float* b2     = (const float*)d_in[9];
    const float* fc_w   = (const float*)d_in[10];
    const float* fc_b   = (const float*)d_in[11];
    float*       out    = (float*)d_out;

    void *p_w1t, *p_w2t, *p_h1h, *p_hh, *p_h2h;
    void *p_as1, *p_ad1, *p_as2, *p_ad2, *p_deg;
    cudaGetSymbolAddress(&p_w1t, g_w1t);
    cudaGetSymbolAddress(&p_w2t, g_w2t);
    cudaGetSymbolAddress(&p_h1h, g_h1h);
    cudaGetSymbolAddress(&p_hh,  g_hh);
    cudaGetSymbolAddress(&p_h2h, g_h2h);
    cudaGetSymbolAddress(&p_as1, g_as1);
    cudaGetSymbolAddress(&p_ad1, g_ad1);
    cudaGetSymbolAddress(&p_as2, g_as2);
    cudaGetSymbolAddress(&p_ad2, g_ad2);
    cudaGetSymbolAddress(&p_deg, g_deg);

    static cudaStream_t s2 = nullptr;
    static cudaEvent_t ev_fork = nullptr, ev_join = nullptr;
    if (s2 == nullptr) {
        cudaStreamCreateWithFlags(&s2, cudaStreamNonBlocking);
        cudaEventCreateWithFlags(&ev_fork, cudaEventDisableTiming);
        cudaEventCreateWithFlags(&ev_join, cudaEventDisableTiming);
    }

    const int MB = (N_NODES + BMg - 1) / BMg;  // 391
    const int EB4 = (N_EDGES / 4 + 255) / 256; // 782
    const int WB = (W1Q + W2Q + 255) / 256;    // 48

    // ---- fork: CSR chain on s2 -------------------------------------------
    cudaEventRecord(ev_fork, 0);
    cudaStreamWaitEvent(s2, ev_fork, 0);
    cudaMemsetAsync(p_deg, 0, N_NODES * sizeof(int), s2);
    k_hist<<<EB4, 256, 0, s2>>>(ei);
    k_scan<<<1, 1024, 0, s2>>>();
    k_fill<<<EB4, 256, 0, s2>>>(ei);
    cudaEventRecord(ev_join, s2);

    // ---- main stream: weight pre-round + GEMM1 (A converted in-smem) -----
    k_cvt_w<<<WB, 256>>>(W1, W2);
    k_gemm_tf32<IN_DIM, HEADS, true><<<dim3(HEADS, MB), 256>>>(
        x, (const float*)p_w1t, (__half*)p_h1h,
        a_src1, a_dst1, (float*)p_as1, (float*)p_ad1);

    // ---- join, then the dependent tail -----------------------------------
    cudaStreamWaitEvent(0, ev_join, 0);
    k_agg1<<<(N_NODES + 7) / 8, 256>>>(b1);
    k_gemm_tf32<H1DIM, 1, false><<<dim3(1, MB), 256>>>(
        (const float*)p_hh, (const float*)p_w2t, (__half*)p_h2h,
        a_src2, a_dst2, (float*)p_as2, (float*)p_ad2);
    k_agg2<<<(N_NODES + 7) / 8, 256>>>(b2, fc_w, fc_b, out);
}

// round 9
// speedup vs baseline: 1.0397x; 1.0397x over previous
#include <cuda_runtime.h>
#include <cuda_fp16.h>
#include <math.h>

// ---------------------------------------------------------------------------
// Problem constants
// ---------------------------------------------------------------------------
#define N_NODES 50000
#define N_EDGES 800000
#define IN_DIM  128
#define HID     64
#define HEADS   4
#define H1DIM   (HEADS * HID)   // 256
#define OUT_DIM 64
#define NEG_SLOPE 0.2f

// ---------------------------------------------------------------------------
// Device scratch
// ---------------------------------------------------------------------------
__device__ float  g_w1t[IN_DIM * H1DIM];           // tf32-rounded W1
__device__ float  g_w2t[H1DIM * OUT_DIM];          // tf32-rounded W2
__device__ __half g_h1h[(size_t)N_NODES * H1DIM];   // x @ W1 (fp16, for gather)
__device__ float  g_hh [(size_t)N_NODES * H1DIM];   // elu(agg1+b1), tf32-rounded
__device__ __half g_h2h[(size_t)N_NODES * OUT_DIM]; // hh @ W2 (fp16, for gather)
__device__ float g_as1[N_NODES * HEADS];
__device__ float g_ad1[N_NODES * HEADS];
__device__ float g_as2[N_NODES];
__device__ float g_ad2[N_NODES];
__device__ int   g_deg[N_NODES];
__device__ int   g_rowptr[N_NODES + 1];
__device__ int   g_cursor[N_NODES];
__device__ int   g_esrc[N_EDGES];

__device__ __forceinline__ unsigned f2tf32(float f) {
    unsigned r;
    asm("cvt.rna.tf32.f32 %0, %1;" : "=r"(r) : "f"(f));
    return r;
}
__device__ __forceinline__ float tf32r(float f) {
    return __uint_as_float(f2tf32(f));
}

// ---------------------------------------------------------------------------
// One-shot tf32 pre-rounding of the WEIGHTS only (x is converted in-smem
// inside GEMM1). 48K elements, ~4us at tiny occupancy.
// ---------------------------------------------------------------------------
#define W1Q  ((IN_DIM * H1DIM) / 4)
#define W2Q  ((H1DIM * OUT_DIM) / 4)

__global__ void k_cvt_w(const float* __restrict__ W1,
                        const float* __restrict__ W2) {
    int i = blockIdx.x * blockDim.x + threadIdx.x;
    if (i >= W1Q + W2Q) return;
    const float4* src;
    float4* dst;
    if (i < W1Q) { src = (const float4*)W1 + i;        dst = (float4*)g_w1t + i; }
    else         { src = (const float4*)W2 + (i - W1Q); dst = (float4*)g_w2t + (i - W1Q); }
    float4 v = *src;
    *dst = make_float4(tf32r(v.x), tf32r(v.y), tf32r(v.z), tf32r(v.w));
}

// ---------------------------------------------------------------------------
// CSR build (edge_index arrives as int32; 4 edges/thread for ILP)
// ---------------------------------------------------------------------------
__global__ void k_hist(const int* __restrict__ ei) {
    int base = (blockIdx.x * blockDim.x + threadIdx.x) * 4;
    if (base >= N_EDGES) return;
    int4 d = *(const int4*)(ei + N_EDGES + base);
    atomicAdd(&g_deg[d.x], 1);
    atomicAdd(&g_deg[d.y], 1);
    atomicAdd(&g_deg[d.z], 1);
    atomicAdd(&g_deg[d.w], 1);
}

__global__ void k_scan() {
    __shared__ int sums[1024];
    const int tid = threadIdx.x;
    const int CH = (N_NODES + 1023) / 1024;
    int start = tid * CH;
    int s = 0;
    for (int i = 0; i < CH; i++) {
        int g = start + i;
        if (g < N_NODES) s += g_deg[g];
    }
    sums[tid] = s;
    __syncthreads();
    for (int off = 1; off < 1024; off <<= 1) {
        int v = (tid >= off) ? sums[tid - off] : 0;
        __syncthreads();
        sums[tid] += v;
        __syncthreads();
    }
    int run = (tid == 0) ? 0 : sums[tid - 1];
    for (int i = 0; i < CH; i++) {
        int g = start + i;
        if (g < N_NODES) {
            g_rowptr[g] = run;
            g_cursor[g] = run;
            run += g_deg[g];
        }
    }
    if (tid == 1023) g_rowptr[N_NODES] = run;
}

__global__ void k_fill(const int* __restrict__ ei) {
    int base = (blockIdx.x * blockDim.x + threadIdx.x) * 4;
    if (base >= N_EDGES) return;
    int4 sv = *(const int4*)(ei + base);
    int4 dv = *(const int4*)(ei + N_EDGES + base);
    int p0 = atomicAdd(&g_cursor[dv.x], 1);
    int p1 = atomicAdd(&g_cursor[dv.y], 1);
    int p2 = atomicAdd(&g_cursor[dv.z], 1);
    int p3 = atomicAdd(&g_cursor[dv.w], 1);
    g_esrc[p0] = sv.x;
    g_esrc[p1] = sv.y;
    g_esrc[p2] = sv.z;
    g_esrc[p3] = sv.w;
}

// ---------------------------------------------------------------------------
// TF32 tensor-core GEMM. Block 128x64, 8 warps (4x2), warp tile 32x32,
// mma.sync.m16n8k8, cp.async 2-stage pipeline.
// CVT_A: convert the A tile to tf32 IN SMEM once per tile (bit-identical to
// fragment-time rounding, each element converted once). B always pre-rounded.
// Epilogue: fp16 H store + fused attention dots (one head == one col block).
// ---------------------------------------------------------------------------
#define BMg 128
#define BNg 64
#define BKg 32

__device__ __forceinline__ void cp16(unsigned dst, const float* src, bool valid) {
    int sz = valid ? 16 : 0;
    asm volatile("cp.async.cg.shared.global [%0], [%1], 16, %2;\n"
                 :: "r"(dst), "l"(src), "r"(sz));
}
#define CP_COMMIT() asm volatile("cp.async.commit_group;\n" ::: "memory")
#define CP_WAIT0()  asm volatile("cp.async.wait_group 0;\n" ::: "memory")

template <int K, int HEADS_N, bool CVT_A>
__global__ void __launch_bounds__(256) k_gemm_tf32(
    const float* __restrict__ A, const float* __restrict__ B,
    __half* __restrict__ Hout,
    const float* __restrict__ a_src, const float* __restrict__ a_dst,
    float* __restrict__ as_out, float* __restrict__ ad_out)
{
    constexpr int NIT = K / BKg;
    __shared__ __align__(16) float As[2][BMg][BKg + 4];
    __shared__ __align__(16) float Bs[2][BKg][BNg + 8];
    __shared__ float sa[64], sd[64];
    __shared__ float ps_s[2][BMg], pd_s[2][BMg];

    const int tid  = threadIdx.x;
    const int head = blockIdx.x;
    const int row0 = blockIdx.y * BMg;
    const int col0 = head * BNg;
    const int NTOT = HEADS_N * 64;
    const int wid = tid >> 5, lane = tid & 31;
    const int wm = wid & 3, wn = wid >> 2;
    const int g = lane >> 2, t4 = lane & 3;

    if (tid < 64) {
        sa[tid] = a_src[head * 64 + tid];
        sd[tid] = a_dst[head * 64 + tid];
    }

    const int ar = tid >> 3;          // 0..31
    const int ac = (tid & 7) * 4;     // 0..28
    const int br = tid >> 4;          // 0..15
    const int bc = (tid & 15) * 4;    // 0..60

    const unsigned sA = (unsigned)__cvta_generic_to_shared(&As[0][0][0]);
    const unsigned sB = (unsigned)__cvta_generic_to_shared(&Bs[0][0][0]);

    float acc[2][4][4];
#pragma unroll
    for (int i = 0; i < 2; i++)
#pragma unroll
        for (int j = 0; j < 4; j++)
#pragma unroll
            for (int c = 0; c < 4; c++) acc[i][j][c] = 0.f;

    auto issue = [&](int it, int buf) {
        const int kt = it * BKg;
#pragma unroll
        for (int i = 0; i < 4; i++) {
            int r = ar + i * 32;
            int grr = row0 + r;
            bool ok = (grr < N_NODES);
            const float* src = A + (size_t)(ok ? grr : 0) * K + kt + ac;
            cp16(sA + (unsigned)(((buf * BMg + r) * (BKg + 4) + ac) * 4), src, ok);
        }
#pragma unroll
        for (int i = 0; i < 2; i++) {
            int r = br + i * 16;
            const float* src = B + (size_t)(kt + r) * NTOT + col0 + bc;
            cp16(sB + (unsigned)(((buf * BKg + r) * (BNg + 8) + bc) * 4), src, true);
        }
    };

    issue(0, 0);
    CP_COMMIT();

    for (int it = 0; it < NIT; it++) {
        CP_WAIT0();
        __syncthreads();
        const int b = it & 1;
        if (CVT_A) {
            // round own A elements in place (overlaps with next-tile issue)
#pragma unroll
            for (int i = 0; i < 4; i++) {
                float4* pp = (float4*)&As[b][ar + i * 32][ac];
                float4 v = *pp;
                *pp = make_float4(tf32r(v.x), tf32r(v.y), tf32r(v.z), tf32r(v.w));
            }
        }
        if (it + 1 < NIT) {
            issue(it + 1, (it + 1) & 1);
            CP_COMMIT();
        }
        if (CVT_A) __syncthreads();   // conversions visible to all warps
#pragma unroll
        for (int kk = 0; kk < BKg; kk += 8) {
            unsigned af[2][4], bf[4][2];
#pragma unroll
            for (int mf = 0; mf < 2; mf++) {
                int rb = wm * 32 + mf * 16 + g;
                af[mf][0] = __float_as_uint(As[b][rb][kk + t4]);
                af[mf][1] = __float_as_uint(As[b][rb + 8][kk + t4]);
                af[mf][2] = __float_as_uint(As[b][rb][kk + t4 + 4]);
                af[mf][3] = __float_as_uint(As[b][rb + 8][kk + t4 + 4]);
            }
#pragma unroll
            for (int nf = 0; nf < 4; nf++) {
                int n = wn * 32 + nf * 8 + g;
                bf[nf][0] = __float_as_uint(Bs[b][kk + t4][n]);
                bf[nf][1] = __float_as_uint(Bs[b][kk + t4 + 4][n]);
            }
#pragma unroll
            for (int mf = 0; mf < 2; mf++)
#pragma unroll
                for (int nf = 0; nf < 4; nf++) {
                    asm volatile(
                        "mma.sync.aligned.m16n8k8.row.col.f32.tf32.tf32.f32 "
                        "{%0,%1,%2,%3}, {%4,%5,%6,%7}, {%8,%9}, {%0,%1,%2,%3};"
                        : "+f"(acc[mf][nf][0]), "+f"(acc[mf][nf][1]),
                          "+f"(acc[mf][nf][2]), "+f"(acc[mf][nf][3])
                        : "r"(af[mf][0]), "r"(af[mf][1]),
                          "r"(af[mf][2]), "r"(af[mf][3]),
                          "r"(bf[nf][0]), "r"(bf[nf][1]));
                }
        }
    }

    // ---- epilogue: attention dots + fp16 store ----------------------------
    float ps[4] = {0.f, 0.f, 0.f, 0.f}, pd[4] = {0.f, 0.f, 0.f, 0.f};
#pragma unroll
    for (int nf = 0; nf < 4; nf++) {
        int cl = wn * 32 + nf * 8 + 2 * t4;
        float s0 = sa[cl], s1 = sa[cl + 1];
        float d0 = sd[cl], d1 = sd[cl + 1];
#pragma unroll
        for (int mf = 0; mf < 2; mf++) {
            ps[mf * 2 + 0] += acc[mf][nf][0] * s0 + acc[mf][nf][1] * s1;
            ps[mf * 2 + 1] += acc[mf][nf][2] * s0 + acc[mf][nf][3] * s1;
            pd[mf * 2 + 0] += acc[mf][nf][0] * d0 + acc[mf][nf][1] * d1;
            pd[mf * 2 + 1] += acc[mf][nf][2] * d0 + acc[mf][nf][3] * d1;
        }
    }
#pragma unroll
    for (int off = 1; off <= 2; off <<= 1)
#pragma unroll
        for (int i = 0; i < 4; i++) {
            ps[i] += __shfl_xor_sync(~0u, ps[i], off);
            pd[i] += __shfl_xor_sync(~0u, pd[i], off);
        }
    if (t4 == 0) {
        int rb = wm * 32 + g;
        ps_s[wn][rb]      = ps[0]; pd_s[wn][rb]      = pd[0];
        ps_s[wn][rb + 8]  = ps[1]; pd_s[wn][rb + 8]  = pd[1];
        ps_s[wn][rb + 16] = ps[2]; pd_s[wn][rb + 16] = pd[2];
        ps_s[wn][rb + 24] = ps[3]; pd_s[wn][rb + 24] = pd[3];
    }

#pragma unroll
    for (int mf = 0; mf < 2; mf++)
#pragma unroll
        for (int nf = 0; nf < 4; nf++) {
            int r = row0 + wm * 32 + mf * 16 + g;
            int c = col0 + wn * 32 + nf * 8 + 2 * t4;
            if (r < N_NODES)
                *(__half2*)(Hout + (size_t)r * NTOT + c) =
                    __floats2half2_rn(acc[mf][nf][0], acc[mf][nf][1]);
            if (r + 8 < N_NODES)
                *(__half2*)(Hout + (size_t)(r + 8) * NTOT + c) =
                    __floats2half2_rn(acc[mf][nf][2], acc[mf][nf][3]);
        }

    __syncthreads();
    if (tid < BMg) {
        int grr = row0 + tid;
        if (grr < N_NODES) {
            as_out[grr * HEADS_N + head] = ps_s[0][tid] + ps_s[1][tid];
            ad_out[grr * HEADS_N + head] = pd_s[0][tid] + pd_s[1][tid];
        }
    }
}

// ---------------------------------------------------------------------------
// Layer-1 aggregation: EXACT round-4 proven form (any inner-loop
// restructuring measured slower three times). Warp per destination node,
// single softmax pass; hh store tf32-pre-rounded for gemm2.
// ---------------------------------------------------------------------------
__global__ void k_agg1(const float* __restrict__ b1) {
    int d = (blockIdx.x * blockDim.x + threadIdx.x) >> 5;
    if (d >= N_NODES) return;
    int lane = threadIdx.x & 31;
    int row  = g_rowptr[d];
    int tot  = g_rowptr[d + 1] - row + 1;     // +1 self-loop
    const int headA = lane & 3;               // phase head
    const int slotA = lane >> 2;              // phase edge slot (0..7)
    const int headB = lane >> 3;              // dim head

    const float ad_h = g_ad1[d * HEADS + headA];

    float ssum = 0.f;
    float acc[8];
#pragma unroll
    for (int j = 0; j < 8; j++) acc[j] = 0.f;

    for (int base = 0; base < tot; base += 8) {
        int idx = base + slotA;
        int s = d;
        float p = 0.f;
        if (idx < tot) {
            if (idx > 0) s = g_esrc[row + idx - 1];
            float v = g_as1[s * HEADS + headA] + ad_h;
            float e = v > 0.f ? v : NEG_SLOPE * v;
            p = __expf(e);
        }
        ssum += p;
        int lim = min(8, tot - base);
        for (int e2 = 0; e2 < lim; e2++) {
            float pe = __shfl_sync(~0u, p, e2 * 4 + headB);
            int   sn = __shfl_sync(~0u, s, e2 * 4);
            uint4 u = *((const uint4*)(g_h1h + (size_t)sn * H1DIM) + lane);
            float2 f0 = __half22float2(*(__half2*)&u.x);
            float2 f1 = __half22float2(*(__half2*)&u.y);
            float2 f2 = __half22float2(*(__half2*)&u.z);
            float2 f3 = __half22float2(*(__half2*)&u.w);
            acc[0] += pe * f0.x; acc[1] += pe * f0.y;
            acc[2] += pe * f1.x; acc[3] += pe * f1.y;
            acc[4] += pe * f2.x; acc[5] += pe * f2.y;
            acc[6] += pe * f3.x; acc[7] += pe * f3.y;
        }
    }
    ssum += __shfl_xor_sync(~0u, ssum, 4);
    ssum += __shfl_xor_sync(~0u, ssum, 8);
    ssum += __shfl_xor_sync(~0u, ssum, 16);     // total for head (lane&3)
    float den = __shfl_sync(~0u, ssum, headB);  // den for this lane's dim-head
    float inv = 1.f / den;

    float* o = g_hh + (size_t)d * H1DIM + lane * 8;
#pragma unroll
    for (int j = 0; j < 8; j++) {
        float v = acc[j] * inv + b1[lane * 8 + j];
        v = v > 0.f ? v : expm1f(v);             // ELU
        o[j] = tf32r(v);                         // pre-round for gemm2
    }
}

// ---------------------------------------------------------------------------
// Layer-2 aggregation + final fc: EXACT round-4 proven form.
// ---------------------------------------------------------------------------
__global__ void k_agg2(const float* __restrict__ b2,
                       const float* __restrict__ fcw,
                       const float* __restrict__ fcb,
                       float* __restrict__ out) {
    int d = (blockIdx.x * blockDim.x + threadIdx.x) >> 5;
    if (d >= N_NODES) return;
    int lane = threadIdx.x & 31;
    int row  = g_rowptr[d];
    int tot  = g_rowptr[d + 1] - row + 1;
    const float ad = g_ad2[d];

    float ssum = 0.f, a0 = 0.f, a1 = 0.f;
    for (int base = 0; base < tot; base += 32) {
        int idx = base + lane;
        int s = d;
        float p = 0.f;
        if (idx < tot) {
            if (idx > 0) s = g_esrc[row + idx - 1];
            float v = g_as2[s] + ad;
            float e = v > 0.f ? v : NEG_SLOPE * v;
            p = __expf(e);
        }
        ssum += p;
        int lim = min(32, tot - base);
        for (int e2 = 0; e2 < lim; e2++) {
            float pe = __shfl_sync(~0u, p, e2);
            int   sn = __shfl_sync(~0u, s, e2);
            float2 hv = __half22float2(
                *((const __half2*)(g_h2h + (size_t)sn * OUT_DIM) + lane));
            a0 += pe * hv.x;
            a1 += pe * hv.y;
        }
    }
#pragma unroll
    for (int off = 16; off >= 1; off >>= 1)
        ssum += __shfl_xor_sync(~0u, ssum, off);
    float inv = 1.f / ssum;
    float v0 = a0 * inv + b2[lane * 2];
    float v1 = a1 * inv + b2[lane * 2 + 1];
    float part = v0 * fcw[lane * 2] + v1 * fcw[lane * 2 + 1];
#pragma unroll
    for (int off = 16; off >= 1; off >>= 1)
        part += __shfl_xor_sync(~0u, part, off);
    if (lane == 0) out[d] = part + fcb[0];
}

// ---------------------------------------------------------------------------
// Launch: fork-join — CSR on side stream ∥ (W-cvt + GEMM1) on main stream.
// ---------------------------------------------------------------------------
extern "C" void kernel_launch(void* const* d_in, const int* in_sizes, int n_in,
                              void* d_out, int out_size) {
    const float* x      = (const float*)d_in[0];
    const int*   ei     = (const int*)d_in[1];     // int32 on the wire
    const float* W1     = (const float*)d_in[2];
    const float* a_src1 = (const float*)d_in[3];
    const float* a_dst1 = (const float*)d_in[4];
    const float* b1     = (const float*)d_in[5];
    const float* W2     = (const float*)d_in[6];
    const float* a_src2 = (const float*)d_in[7];
    const float* a_dst2 = (const float*)d_in[8];
    const float* b2     = (const float*)d_in[9];
    const float* fc_w   = (const float*)d_in[10];
    const float* fc_b   = (const float*)d_in[11];
    float*       out    = (float*)d_out;

    void *p_w1t, *p_w2t, *p_h1h, *p_hh, *p_h2h;
    void *p_as1, *p_ad1, *p_as2, *p_ad2, *p_deg;
    cudaGetSymbolAddress(&p_w1t, g_w1t);
    cudaGetSymbolAddress(&p_w2t, g_w2t);
    cudaGetSymbolAddress(&p_h1h, g_h1h);
    cudaGetSymbolAddress(&p_hh,  g_hh);
    cudaGetSymbolAddress(&p_h2h, g_h2h);
    cudaGetSymbolAddress(&p_as1, g_as1);
    cudaGetSymbolAddress(&p_ad1, g_ad1);
    cudaGetSymbolAddress(&p_as2, g_as2);
    cudaGetSymbolAddress(&p_ad2, g_ad2);
    cudaGetSymbolAddress(&p_deg, g_deg);

    static cudaStream_t s2 = nullptr;
    static cudaEvent_t ev_fork = nullptr, ev_join = nullptr;
    if (s2 == nullptr) {
        cudaStreamCreateWithFlags(&s2, cudaStreamNonBlocking);
        cudaEventCreateWithFlags(&ev_fork, cudaEventDisableTiming);
        cudaEventCreateWithFlags(&ev_join, cudaEventDisableTiming);
    }

    const int MB = (N_NODES + BMg - 1) / BMg;  // 391
    const int EB4 = (N_EDGES / 4 + 255) / 256; // 782
    const int WB = (W1Q + W2Q + 255) / 256;    // 48

    // ---- fork: CSR chain on s2 -------------------------------------------
    cudaEventRecord(ev_fork, 0);
    cudaStreamWaitEvent(s2, ev_fork, 0);
    cudaMemsetAsync(p_deg, 0, N_NODES * sizeof(int), s2);
    k_hist<<<EB4, 256, 0, s2>>>(ei);
    k_scan<<<1, 1024, 0, s2>>>();
    k_fill<<<EB4, 256, 0, s2>>>(ei);
    cudaEventRecord(ev_join, s2);

    // ---- main stream: weight pre-round + GEMM1 (A converted in-smem) -----
    k_cvt_w<<<WB, 256>>>(W1, W2);
    k_gemm_tf32<IN_DIM, HEADS, true><<<dim3(HEADS, MB), 256>>>(
        x, (const float*)p_w1t, (__half*)p_h1h,
        a_src1, a_dst1, (float*)p_as1, (float*)p_ad1);

    // ---- join, then the dependent tail -----------------------------------
    cudaStreamWaitEvent(0, ev_join, 0);
    k_agg1<<<(N_NODES + 7) / 8, 256>>>(b1);
    k_gemm_tf32<H1DIM, 1, false><<<dim3(1, MB), 256>>>(
        (const float*)p_hh, (const float*)p_w2t, (__half*)p_h2h,
        a_src2, a_dst2, (float*)p_as2, (float*)p_ad2);
    k_agg2<<<(N_NODES + 7) / 8, 256>>>(b2, fc_w, fc_b, out);
}